// round 1
// baseline (speedup 1.0000x reference)
#include <cuda_runtime.h>
#include <math.h>

// Problem constants
#define BB    64
#define NN    2048
#define DIN   2
#define DOUT  64
#define DD    10
#define CIN   66          // DIN + DOUT
#define KJ    132         // CHEB_K * CIN
#define GOUT  128         // gate output (2*DOUT)
#define UOUT  64          // update output
#define NCOLS (BB*CIN)    // 4224

// -------- scratch (device globals; no allocation allowed) --------
__device__ float g_S   [NN*NN];          // softmax(relu(E E^T))  [n][m]
__device__ float g_xin [NN*BB*CIN];      // concat(x,state)       [n][b][c]
__device__ float g_xg1 [NN*BB*CIN];      // S @ xin               [n][b][c]
__device__ float g_cand[NN*BB*CIN];      // concat(x, z*state)    [n][b][c]
__device__ float g_cg1 [NN*BB*CIN];      // S @ cand              [n][b][c]
__device__ float g_r   [NN*BB*DOUT];     // reset gate            [n][b][o]
__device__ float g_Wg  [NN*KJ*GOUT];     // pooled gate weights   [n][j][o]
__device__ float g_Wu  [NN*KJ*UOUT];     // pooled update weights [n][j][o]
__device__ float g_bg  [NN*GOUT];        // pooled gate bias
__device__ float g_bu  [NN*UOUT];        // pooled update bias

// ---------------------------------------------------------------
// K1: supports = softmax(relu(E @ E^T), axis=1). One block per row.
// ---------------------------------------------------------------
__global__ __launch_bounds__(256) void supports_kernel(const float* __restrict__ E) {
    const int n   = blockIdx.x;
    const int tid = threadIdx.x;
    __shared__ float en[DD];
    __shared__ float red[256];

    if (tid < DD) en[tid] = E[n*DD + tid];
    __syncthreads();

    float vals[8];
    float vmax = -1e30f;
    #pragma unroll
    for (int i = 0; i < 8; i++) {
        int m = i*256 + tid;
        float dot = 0.f;
        #pragma unroll
        for (int d = 0; d < DD; d++) dot += en[d] * E[m*DD + d];
        float v = dot > 0.f ? dot : 0.f;   // relu
        vals[i] = v;
        vmax = fmaxf(vmax, v);
    }
    // block max
    red[tid] = vmax; __syncthreads();
    for (int s = 128; s > 0; s >>= 1) {
        if (tid < s) red[tid] = fmaxf(red[tid], red[tid + s]);
        __syncthreads();
    }
    vmax = red[0]; __syncthreads();

    float lsum = 0.f;
    #pragma unroll
    for (int i = 0; i < 8; i++) { vals[i] = expf(vals[i] - vmax); lsum += vals[i]; }

    red[tid] = lsum; __syncthreads();
    for (int s = 128; s > 0; s >>= 1) {
        if (tid < s) red[tid] += red[tid + s];
        __syncthreads();
    }
    const float inv = 1.f / red[0];

    #pragma unroll
    for (int i = 0; i < 8; i++)
        g_S[(size_t)n*NN + i*256 + tid] = vals[i] * inv;
}

// ---------------------------------------------------------------
// K2: xin[n][b][c] = (c<2) ? x[b][n][c] : state[b][n][c-2]
// ---------------------------------------------------------------
__global__ __launch_bounds__(256) void concat_kernel(const float* __restrict__ x,
                                                     const float* __restrict__ state) {
    int idx = blockIdx.x * 256 + threadIdx.x;
    if (idx >= NN*BB*CIN) return;
    int c  = idx % CIN;
    int nb = idx / CIN;
    int b  = nb % BB;
    int n  = nb / BB;
    float v = (c < DIN) ? x[((size_t)b*NN + n)*DIN + c]
                        : state[((size_t)b*NN + n)*DOUT + (c - DIN)];
    g_xin[idx] = v;
}

// ---------------------------------------------------------------
// K3: pooled weight gen. W[n][idx] = sum_d E[n,d] * wpool[d][idx].
// Each thread fixes a weight position, loops 16 nodes (keeps wpool
// reads 16x lower). which: 0 -> gate, 1 -> update.
// ---------------------------------------------------------------
__global__ __launch_bounds__(256) void wgen_kernel(const float* __restrict__ E,
                                                   const float* __restrict__ wpool,
                                                   int KO, int which) {
    int idx = blockIdx.x * 256 + threadIdx.x;
    if (idx >= KO) return;
    float* Wout = which ? g_Wu : g_Wg;
    float w[DD];
    #pragma unroll
    for (int d = 0; d < DD; d++) w[d] = wpool[d*KO + idx];
    int n0 = blockIdx.y * 16;
    #pragma unroll 4
    for (int nn = 0; nn < 16; nn++) {
        int n = n0 + nn;
        float s = 0.f;
        #pragma unroll
        for (int d = 0; d < DD; d++) s += E[n*DD + d] * w[d];
        Wout[(size_t)n*KO + idx] = s;
    }
}

__global__ __launch_bounds__(256) void bgen_kernel(const float* __restrict__ E,
                                                   const float* __restrict__ bpool,
                                                   int OUT, int which) {
    int idx = blockIdx.x * 256 + threadIdx.x;
    if (idx >= NN*OUT) return;
    float* bout = which ? g_bu : g_bg;
    int n = idx / OUT, o = idx % OUT;
    float s = 0.f;
    #pragma unroll
    for (int d = 0; d < DD; d++) s += E[n*DD + d] * bpool[d*OUT + o];
    bout[idx] = s;
}

// ---------------------------------------------------------------
// K4: big SGEMM  C[2048, 4224] = g_S[2048,2048] @ B[2048,4224]
// pass 0: B = g_xin  -> C = g_xg1
// pass 1: B = g_cand -> C = g_cg1
// 128x128 tile, BK=8, 256 threads, 8x8 microtile.
// ---------------------------------------------------------------
__global__ __launch_bounds__(256) void sgemm_kernel(int pass) {
    const float* __restrict__ A  = g_S;
    const float* __restrict__ Bm = pass ? g_cand : g_xin;
    float* __restrict__       C  = pass ? g_cg1  : g_xg1;

    __shared__ float As[8][128];
    __shared__ float Bs[8][128];

    const int tid = threadIdx.x;
    const int bx = blockIdx.x, by = blockIdx.y;
    const int tx = tid & 15, ty = tid >> 4;
    const int row0 = by*128 + ty*8;
    const int colb = bx*128;
    const int col0 = tx*8;

    const int arow = tid >> 1;
    const int acol = (tid & 1) * 4;
    const int brow = tid >> 5;
    const int bcol = (tid & 31) * 4;

    const float* Aptr = A  + (size_t)(by*128 + arow)*NN + acol;
    const float* Bptr = Bm + (size_t)brow*NCOLS + colb + bcol;

    float acc[8][8];
    #pragma unroll
    for (int i = 0; i < 8; i++)
        #pragma unroll
        for (int j = 0; j < 8; j++) acc[i][j] = 0.f;

    for (int kt = 0; kt < NN; kt += 8) {
        float4 av = *(const float4*)(Aptr + kt);
        As[acol+0][arow] = av.x; As[acol+1][arow] = av.y;
        As[acol+2][arow] = av.z; As[acol+3][arow] = av.w;
        *(float4*)&Bs[brow][bcol] = *(const float4*)(Bptr + (size_t)kt*NCOLS);
        __syncthreads();
        #pragma unroll
        for (int k = 0; k < 8; k++) {
            float a[8], b[8];
            *(float4*)&a[0] = *(float4*)&As[k][ty*8];
            *(float4*)&a[4] = *(float4*)&As[k][ty*8 + 4];
            *(float4*)&b[0] = *(float4*)&Bs[k][col0];
            *(float4*)&b[4] = *(float4*)&Bs[k][col0 + 4];
            #pragma unroll
            for (int i = 0; i < 8; i++)
                #pragma unroll
                for (int j = 0; j < 8; j++)
                    acc[i][j] += a[i] * b[j];
        }
        __syncthreads();
    }
    #pragma unroll
    for (int i = 0; i < 8; i++) {
        float* Crow = C + (size_t)(row0 + i)*NCOLS + colb + col0;
        *(float4*)&Crow[0] = make_float4(acc[i][0], acc[i][1], acc[i][2], acc[i][3]);
        *(float4*)&Crow[4] = make_float4(acc[i][4], acc[i][5], acc[i][6], acc[i][7]);
    }
}

// ---------------------------------------------------------------
// K5: gate per-node GEMM + sigmoid + candidate build.
// Block n: ZR[64,128] = [xin[n] | xg1[n]] (64x132) @ Wg[n] (132x128) + bg[n]
// z = sig(ZR[:, :64]) -> cand[n][b][2+o] = z * state
// r = sig(ZR[:, 64:]) -> g_r
// cand[n][b][0:2] = x[b][n][:]
// smem: W (132*128) + A (64*132) = 101376 bytes (dynamic)
// ---------------------------------------------------------------
__global__ __launch_bounds__(256) void gate_kernel(const float* __restrict__ x,
                                                   const float* __restrict__ state) {
    extern __shared__ float sm[];
    float* sW = sm;              // [KJ][GOUT]
    float* sA = sm + KJ*GOUT;    // [BB][KJ]

    const int n   = blockIdx.x;
    const int tid = threadIdx.x;

    const float* Wn = g_Wg + (size_t)n*KJ*GOUT;
    for (int i = tid*4; i < KJ*GOUT; i += 1024)
        *(float4*)&sW[i] = *(const float4*)&Wn[i];

    const float* xin_n = g_xin + (size_t)n*BB*CIN;
    const float* xg1_n = g_xg1 + (size_t)n*BB*CIN;
    for (int i = tid; i < BB*KJ; i += 256) {
        int b = i / KJ, j = i % KJ;
        sA[i] = (j < CIN) ? xin_n[b*CIN + j] : xg1_n[b*CIN + (j - CIN)];
    }
    __syncthreads();

    const int ty = tid >> 5, tx = tid & 31;
    const int row0 = ty*8;      // batch rows
    const int col0 = tx*4;      // output cols

    float acc[8][4];
    #pragma unroll
    for (int i = 0; i < 8; i++)
        #pragma unroll
        for (int j = 0; j < 4; j++) acc[i][j] = 0.f;

    for (int kk = 0; kk < KJ; kk++) {
        float4 wv = *(float4*)&sW[kk*GOUT + col0];
        #pragma unroll
        for (int i = 0; i < 8; i++) {
            float av = sA[(row0 + i)*KJ + kk];
            acc[i][0] += av * wv.x;
            acc[i][1] += av * wv.y;
            acc[i][2] += av * wv.z;
            acc[i][3] += av * wv.w;
        }
    }

    #pragma unroll
    for (int j = 0; j < 4; j++) {
        int o = col0 + j;
        float bias = g_bg[n*GOUT + o];
        #pragma unroll
        for (int i = 0; i < 8; i++) {
            int b = row0 + i;
            float v = 1.f / (1.f + expf(-(acc[i][j] + bias)));
            if (o < DOUT) {  // z
                float st = state[((size_t)b*NN + n)*DOUT + o];
                g_cand[((size_t)n*BB + b)*CIN + DIN + o] = v * st;
            } else {         // r
                g_r[((size_t)n*BB + b)*DOUT + (o - DOUT)] = v;
            }
        }
    }
    if (tx == 0) {
        #pragma unroll
        for (int i = 0; i < 8; i++) {
            int b = row0 + i;
            g_cand[((size_t)n*BB + b)*CIN + 0] = x[((size_t)b*NN + n)*DIN + 0];
            g_cand[((size_t)n*BB + b)*CIN + 1] = x[((size_t)b*NN + n)*DIN + 1];
        }
    }
}

// ---------------------------------------------------------------
// K6: update per-node GEMM + tanh + GRU combine -> d_out [B,N,64]
// smem: W (132*64) + A (64*132) = 67584 bytes (dynamic)
// ---------------------------------------------------------------
__global__ __launch_bounds__(256) void update_kernel(const float* __restrict__ state,
                                                     float* __restrict__ out) {
    extern __shared__ float sm[];
    float* sW = sm;              // [KJ][UOUT]
    float* sA = sm + KJ*UOUT;    // [BB][KJ]

    const int n   = blockIdx.x;
    const int tid = threadIdx.x;

    const float* Wn = g_Wu + (size_t)n*KJ*UOUT;
    for (int i = tid*4; i < KJ*UOUT; i += 1024)
        *(float4*)&sW[i] = *(const float4*)&Wn[i];

    const float* ca_n = g_cand + (size_t)n*BB*CIN;
    const float* cg_n = g_cg1  + (size_t)n*BB*CIN;
    for (int i = tid; i < BB*KJ; i += 256) {
        int b = i / KJ, j = i % KJ;
        sA[i] = (j < CIN) ? ca_n[b*CIN + j] : cg_n[b*CIN + (j - CIN)];
    }
    __syncthreads();

    const int ty = tid >> 5, tx = tid & 31;
    const int row0 = ty*8;      // batch rows
    const int col0 = tx*2;      // output cols

    float acc[8][2];
    #pragma unroll
    for (int i = 0; i < 8; i++) { acc[i][0] = 0.f; acc[i][1] = 0.f; }

    for (int kk = 0; kk < KJ; kk++) {
        float2 wv = *(float2*)&sW[kk*UOUT + col0];
        #pragma unroll
        for (int i = 0; i < 8; i++) {
            float av = sA[(row0 + i)*KJ + kk];
            acc[i][0] += av * wv.x;
            acc[i][1] += av * wv.y;
        }
    }

    #pragma unroll
    for (int j = 0; j < 2; j++) {
        int o = col0 + j;
        float bias = g_bu[n*UOUT + o];
        #pragma unroll
        for (int i = 0; i < 8; i++) {
            int b = row0 + i;
            float hc = tanhf(acc[i][j] + bias);
            float r  = g_r[((size_t)n*BB + b)*DOUT + o];
            float st = state[((size_t)b*NN + n)*DOUT + o];
            out[((size_t)b*NN + n)*DOUT + o] = r*st + (1.f - r)*hc;
        }
    }
}

// ---------------------------------------------------------------
extern "C" void kernel_launch(void* const* d_in, const int* in_sizes, int n_in,
                              void* d_out, int out_size) {
    const float* x     = (const float*)d_in[0];  // [B,N,2]
    const float* state = (const float*)d_in[1];  // [B,N,64]
    const float* E     = (const float*)d_in[2];  // [N,10]
    const float* gw    = (const float*)d_in[3];  // [10,2,66,128]
    const float* gb    = (const float*)d_in[4];  // [10,128]
    const float* uw    = (const float*)d_in[5];  // [10,2,66,64]
    const float* ub    = (const float*)d_in[6];  // [10,64]
    float* out = (float*)d_out;

    // dynamic smem > 48KB for the per-node kernels (idempotent; not a stream op)
    cudaFuncSetAttribute(gate_kernel,   cudaFuncAttributeMaxDynamicSharedMemorySize, (KJ*GOUT + BB*KJ)*4);
    cudaFuncSetAttribute(update_kernel, cudaFuncAttributeMaxDynamicSharedMemorySize, (KJ*UOUT + BB*KJ)*4);

    // 1. adjacency supports
    supports_kernel<<<NN, 256>>>(E);
    // 2. concat(x, state) -> node-major
    concat_kernel<<<(NN*BB*CIN + 255)/256, 256>>>(x, state);
    // 3. pooled weights / biases
    wgen_kernel<<<dim3((KJ*GOUT + 255)/256, NN/16), 256>>>(E, gw, KJ*GOUT, 0);
    wgen_kernel<<<dim3((KJ*UOUT + 255)/256, NN/16), 256>>>(E, uw, KJ*UOUT, 1);
    bgen_kernel<<<(NN*GOUT + 255)/256, 256>>>(E, gb, GOUT, 0);
    bgen_kernel<<<(NN*UOUT + 255)/256, 256>>>(E, ub, UOUT, 1);
    // 4. xg1 = S @ xin
    sgemm_kernel<<<dim3(NCOLS/128, NN/128), 256>>>(0);
    // 5. gate: z,r + candidate
    gate_kernel<<<NN, 256, (KJ*GOUT + BB*KJ)*4>>>(x, state);
    // 6. cg1 = S @ cand
    sgemm_kernel<<<dim3(NCOLS/128, NN/128), 256>>>(1);
    // 7. update: hc + GRU combine -> out
    update_kernel<<<NN, 256, (KJ*UOUT + BB*KJ)*4>>>(state, out);
}

// round 3
// speedup vs baseline: 1.7685x; 1.7685x over previous
#include <cuda_runtime.h>
#include <cuda_bf16.h>
#include <math.h>
#include <stdint.h>

// Problem constants
#define BB    64
#define NN    2048
#define DIN   2
#define DOUT  64
#define DD    10
#define CIN   66          // DIN + DOUT
#define KJ    132         // CHEB_K * CIN
#define GOUT  128         // gate output (2*DOUT)
#define UOUT  64          // update output
#define NCOLS (BB*CIN)    // 4224

// ================= PTX helpers (baseline sm_80+ ISA only) =================
__device__ __forceinline__ uint32_t smem_to_u32(const void* smem_ptr) {
    uint32_t addr;
    asm("{ .reg .u64 tmp; cvta.to.shared.u64 tmp, %1; cvt.u32.u64 %0, tmp; }"
        : "=r"(addr) : "l"(smem_ptr));
    return addr;
}
__device__ __forceinline__ void cpasync16(uint32_t dst, const void* src) {
    asm volatile("cp.async.cg.shared.global [%0], [%1], 16;" :: "r"(dst), "l"(src) : "memory");
}
#define CPASYNC_COMMIT() asm volatile("cp.async.commit_group;" ::: "memory")
#define CPASYNC_WAIT(n)  asm volatile("cp.async.wait_group %0;" :: "n"(n) : "memory")

#define LDMX4(r, addr) \
    asm volatile("ldmatrix.sync.aligned.m8n8.x4.shared.b16 {%0,%1,%2,%3}, [%4];" \
        : "=r"((r)[0]), "=r"((r)[1]), "=r"((r)[2]), "=r"((r)[3]) : "r"(addr))

#define MMA_BF16(d, a, b0, b1) \
    asm volatile("mma.sync.aligned.m16n8k16.row.col.f32.bf16.bf16.f32 " \
        "{%0,%1,%2,%3}, {%4,%5,%6,%7}, {%8,%9}, {%0,%1,%2,%3};" \
        : "+f"((d)[0]), "+f"((d)[1]), "+f"((d)[2]), "+f"((d)[3]) \
        : "r"((a)[0]), "r"((a)[1]), "r"((a)[2]), "r"((a)[3]), "r"(b0), "r"(b1))

// -------- scratch (device globals; no allocation allowed) --------
__device__ __align__(128) __nv_bfloat16 g_Shi [NN*NN];        // bf16 hi of supports [m][k]
__device__ __align__(128) __nv_bfloat16 g_Slo [NN*NN];        // bf16 lo
__device__ __align__(128) float g_xin [NN*BB*CIN];            // concat(x,state)  [n][b][c]
__device__ __align__(128) float g_xg1 [NN*BB*CIN];            // S @ xin          [n][b][c]
__device__ __align__(128) float g_cand[NN*BB*CIN];            // concat(x,z*state)[n][b][c]
__device__ __align__(128) float g_cg1 [NN*BB*CIN];            // S @ cand         [n][b][c]
__device__ __align__(128) __nv_bfloat16 g_xt_hi[NCOLS*NN];    // xin^T bf16 hi [col][k]
__device__ __align__(128) __nv_bfloat16 g_xt_lo[NCOLS*NN];
__device__ __align__(128) __nv_bfloat16 g_ct_hi[NCOLS*NN];    // cand^T bf16 hi
__device__ __align__(128) __nv_bfloat16 g_ct_lo[NCOLS*NN];
__device__ __align__(128) float g_r   [NN*BB*DOUT];
__device__ __align__(128) float g_Wg  [NN*KJ*GOUT];
__device__ __align__(128) float g_Wu  [NN*KJ*UOUT];
__device__ __align__(128) float g_bg  [NN*GOUT];
__device__ __align__(128) float g_bu  [NN*UOUT];

// ---------------------------------------------------------------
// K1: supports = softmax(relu(E E^T)) -> bf16 hi/lo split
// ---------------------------------------------------------------
__global__ __launch_bounds__(256) void supports_kernel(const float* __restrict__ E) {
    const int n   = blockIdx.x;
    const int tid = threadIdx.x;
    __shared__ float en[DD];
    __shared__ float red[256];

    if (tid < DD) en[tid] = E[n*DD + tid];
    __syncthreads();

    float vals[8];
    float vmax = -1e30f;
    #pragma unroll
    for (int i = 0; i < 8; i++) {
        int m = i*256 + tid;
        float dot = 0.f;
        #pragma unroll
        for (int d = 0; d < DD; d++) dot += en[d] * E[m*DD + d];
        float v = dot > 0.f ? dot : 0.f;
        vals[i] = v;
        vmax = fmaxf(vmax, v);
    }
    red[tid] = vmax; __syncthreads();
    for (int s = 128; s > 0; s >>= 1) {
        if (tid < s) red[tid] = fmaxf(red[tid], red[tid + s]);
        __syncthreads();
    }
    vmax = red[0]; __syncthreads();

    float lsum = 0.f;
    #pragma unroll
    for (int i = 0; i < 8; i++) { vals[i] = expf(vals[i] - vmax); lsum += vals[i]; }
    red[tid] = lsum; __syncthreads();
    for (int s = 128; s > 0; s >>= 1) {
        if (tid < s) red[tid] += red[tid + s];
        __syncthreads();
    }
    const float inv = 1.f / red[0];

    #pragma unroll
    for (int i = 0; i < 8; i++) {
        float v = vals[i] * inv;
        __nv_bfloat16 h = __float2bfloat16(v);
        __nv_bfloat16 l = __float2bfloat16(v - __bfloat162float(h));
        size_t off = (size_t)n*NN + i*256 + tid;
        g_Shi[off] = h;
        g_Slo[off] = l;
    }
}

// ---------------------------------------------------------------
// K2: xin[n][b][c] = (c<2) ? x[b][n][c] : state[b][n][c-2]
// ---------------------------------------------------------------
__global__ __launch_bounds__(256) void concat_kernel(const float* __restrict__ x,
                                                     const float* __restrict__ state) {
    int idx = blockIdx.x * 256 + threadIdx.x;
    if (idx >= NN*BB*CIN) return;
    int c  = idx % CIN;
    int nb = idx / CIN;
    int b  = nb % BB;
    int n  = nb / BB;
    float v = (c < DIN) ? x[((size_t)b*NN + n)*DIN + c]
                        : state[((size_t)b*NN + n)*DOUT + (c - DIN)];
    g_xin[idx] = v;
}

// ---------------------------------------------------------------
// K2b: transpose+convert: src fp32 [2048][4224] -> hi/lo bf16 [4224][2048]
// ---------------------------------------------------------------
__global__ __launch_bounds__(256) void transconv_kernel(int which) {
    const float* __restrict__ src = which ? g_cand : g_xin;
    __nv_bfloat16* __restrict__ dhi = which ? g_ct_hi : g_xt_hi;
    __nv_bfloat16* __restrict__ dlo = which ? g_ct_lo : g_xt_lo;

    __shared__ float t[64][129];
    const int tid = threadIdx.x;
    const int c0 = blockIdx.x * 64;
    const int n0 = blockIdx.y * 128;

    #pragma unroll
    for (int it = 0; it < 8; it++) {
        int lin = tid + it*256;
        int r = lin >> 4, q = lin & 15;
        float4 v = *(const float4*)&src[(size_t)(n0 + r)*NCOLS + c0 + q*4];
        t[q*4+0][r] = v.x; t[q*4+1][r] = v.y; t[q*4+2][r] = v.z; t[q*4+3][r] = v.w;
    }
    __syncthreads();

    const int j = tid >> 2;
    const int seg = tid & 3;
    alignas(16) __nv_bfloat16 hb[32];
    alignas(16) __nv_bfloat16 lb[32];
    #pragma unroll
    for (int v = 0; v < 32; v++) {
        float f = t[j][seg*32 + v];
        __nv_bfloat16 h = __float2bfloat16(f);
        hb[v] = h;
        lb[v] = __float2bfloat16(f - __bfloat162float(h));
    }
    size_t off = (size_t)(c0 + j)*NN + n0 + seg*32;
    uint4* dh = (uint4*)(dhi + off);
    uint4* dl = (uint4*)(dlo + off);
    const uint4* sh = (const uint4*)hb;
    const uint4* sl = (const uint4*)lb;
    #pragma unroll
    for (int q = 0; q < 4; q++) { dh[q] = sh[q]; dl[q] = sl[q]; }
}

// ---------------------------------------------------------------
// K3: pooled weight/bias gen
// ---------------------------------------------------------------
__global__ __launch_bounds__(256) void wgen_kernel(const float* __restrict__ E,
                                                   const float* __restrict__ wpool,
                                                   int KO, int which) {
    int idx = blockIdx.x * 256 + threadIdx.x;
    if (idx >= KO) return;
    float* Wout = which ? g_Wu : g_Wg;
    float w[DD];
    #pragma unroll
    for (int d = 0; d < DD; d++) w[d] = wpool[d*KO + idx];
    int n0 = blockIdx.y * 16;
    #pragma unroll 4
    for (int nn = 0; nn < 16; nn++) {
        int n = n0 + nn;
        float s = 0.f;
        #pragma unroll
        for (int d = 0; d < DD; d++) s += E[n*DD + d] * w[d];
        Wout[(size_t)n*KO + idx] = s;
    }
}

__global__ __launch_bounds__(256) void bgen_kernel(const float* __restrict__ E,
                                                   const float* __restrict__ bpool,
                                                   int OUT, int which) {
    int idx = blockIdx.x * 256 + threadIdx.x;
    if (idx >= NN*OUT) return;
    float* bout = which ? g_bu : g_bg;
    int n = idx / OUT, o = idx % OUT;
    float s = 0.f;
    #pragma unroll
    for (int d = 0; d < DD; d++) s += E[n*DD + d] * bpool[d*OUT + o];
    bout[idx] = s;
}

// ---------------------------------------------------------------
// K4: HMMA (mma.sync) bf16 split-3 GEMM: C[2048,4224] = S @ X
// A = Shi/Slo [m][k]; B^T = xt/ct hi/lo [col][k]; C fp32 [m][col]
// CTA 128x128, BK=32, 2-stage cp.async, 8 warps (2x4), warp tile 64x32.
// SMEM rows padded to 80B (5x16B; gcd(5,8)=1 -> ldmatrix conflict-free).
// ---------------------------------------------------------------
#define BKC      32
#define NCHUNKS  (NN/BKC)          // 64
#define RSTRIDE  80                // bytes per smem row (40 bf16)
#define TILE_B   (128*RSTRIDE)     // 10240 bytes per tile
#define STAGE_B  (4*TILE_B)        // Ahi,Alo,Bhi,Blo = 40960
#define GEMM_SMEM (2*STAGE_B)      // 81920

__global__ __launch_bounds__(256) void hmma_gemm_kernel(int pass) {
    const __nv_bfloat16* __restrict__ Bthi = pass ? g_ct_hi : g_xt_hi;
    const __nv_bfloat16* __restrict__ Btlo = pass ? g_ct_lo : g_xt_lo;
    float* __restrict__ C = pass ? g_cg1 : g_xg1;

    extern __shared__ char smem[];
    const uint32_t sb = smem_to_u32(smem);
    const int tid  = threadIdx.x;
    const int lane = tid & 31;
    const int wid  = tid >> 5;
    const int m0 = blockIdx.y * 128;
    const int n0 = blockIdx.x * 128;
    const int wm = (wid >> 2) * 64;   // warp m offset in tile
    const int wn = (wid & 3)  * 32;   // warp n offset in tile

    float acc[4][4][4];
    #pragma unroll
    for (int i = 0; i < 4; i++)
        #pragma unroll
        for (int j = 0; j < 4; j++)
            #pragma unroll
            for (int q = 0; q < 4; q++) acc[i][j][q] = 0.f;

    // loader indices: idx in [0,512): row = idx>>2 (0..127), chunk c = idx&3
    const int lrow = tid >> 2;        // rows lrow and lrow+64
    const int lc   = tid & 3;

    // main 2-stage pipeline
    {
        // prolog: stage 0, chunk 0
        #pragma unroll
        for (int h = 0; h < 2; h++) {
            int row = lrow + h*64;
            uint32_t doff = (uint32_t)(row*RSTRIDE + lc*16);
            size_t ga = (size_t)(m0 + row)*NN + lc*8;
            size_t gb = (size_t)(n0 + row)*NN + lc*8;
            cpasync16(sb + 0*TILE_B + doff, g_Shi + ga);
            cpasync16(sb + 1*TILE_B + doff, g_Slo + ga);
            cpasync16(sb + 2*TILE_B + doff, Bthi + gb);
            cpasync16(sb + 3*TILE_B + doff, Btlo + gb);
        }
        CPASYNC_COMMIT();
    }

    for (int kt = 0; kt < NCHUNKS; kt++) {
        if (kt + 1 < NCHUNKS) {
            const uint32_t stg = sb + (uint32_t)(((kt+1) & 1) * STAGE_B);
            const int gk = (kt + 1) * BKC;
            #pragma unroll
            for (int h = 0; h < 2; h++) {
                int row = lrow + h*64;
                uint32_t doff = (uint32_t)(row*RSTRIDE + lc*16);
                size_t ga = (size_t)(m0 + row)*NN + gk + lc*8;
                size_t gb = (size_t)(n0 + row)*NN + gk + lc*8;
                cpasync16(stg + 0*TILE_B + doff, g_Shi + ga);
                cpasync16(stg + 1*TILE_B + doff, g_Slo + ga);
                cpasync16(stg + 2*TILE_B + doff, Bthi + gb);
                cpasync16(stg + 3*TILE_B + doff, Btlo + gb);
            }
            CPASYNC_COMMIT();
            CPASYNC_WAIT(1);
        } else {
            CPASYNC_WAIT(0);
        }
        __syncthreads();

        // ------- compute on stage kt&1 -------
        const uint32_t stg = sb + (uint32_t)((kt & 1) * STAGE_B);
        const int lr16 = lane & 15;
        const int lch  = lane >> 4;
        #pragma unroll
        for (int ks = 0; ks < 2; ks++) {
            uint32_t ahi[4][4], alo[4][4];
            uint32_t aoff = stg + (uint32_t)((wm + lr16)*RSTRIDE + (ks*2 + lch)*16);
            #pragma unroll
            for (int mt = 0; mt < 4; mt++) {
                LDMX4(ahi[mt], aoff + (uint32_t)(mt*16*RSTRIDE));
                LDMX4(alo[mt], aoff + TILE_B + (uint32_t)(mt*16*RSTRIDE));
            }
            uint32_t bhi[2][4], blo[2][4];
            uint32_t boff = stg + 2*TILE_B + (uint32_t)((wn + lr16)*RSTRIDE + (ks*2 + lch)*16);
            #pragma unroll
            for (int np = 0; np < 2; np++) {
                LDMX4(bhi[np], boff + (uint32_t)(np*16*RSTRIDE));
                LDMX4(blo[np], boff + TILE_B + (uint32_t)(np*16*RSTRIDE));
            }
            // pass 1: Ahi*Bhi (16 independent accumulators between reuses)
            #pragma unroll
            for (int mt = 0; mt < 4; mt++)
                #pragma unroll
                for (int nt = 0; nt < 4; nt++) {
                    int np = nt >> 1, sel = nt & 1;
                    MMA_BF16(acc[mt][nt], ahi[mt], bhi[np][sel], bhi[np][sel+2]);
                }
            // pass 2: Ahi*Blo
            #pragma unroll
            for (int mt = 0; mt < 4; mt++)
                #pragma unroll
                for (int nt = 0; nt < 4; nt++) {
                    int np = nt >> 1, sel = nt & 1;
                    MMA_BF16(acc[mt][nt], ahi[mt], blo[np][sel], blo[np][sel+2]);
                }
            // pass 3: Alo*Bhi
            #pragma unroll
            for (int mt = 0; mt < 4; mt++)
                #pragma unroll
                for (int nt = 0; nt < 4; nt++) {
                    int np = nt >> 1, sel = nt & 1;
                    MMA_BF16(acc[mt][nt], alo[mt], bhi[np][sel], bhi[np][sel+2]);
                }
        }
        __syncthreads();
    }

    // ------- epilogue: write fp32 C -------
    const int erow = lane >> 2;          // 0..7
    const int ecol = (lane & 3) * 2;     // 0,2,4,6
    #pragma unroll
    for (int mt = 0; mt < 4; mt++) {
        #pragma unroll
        for (int nt = 0; nt < 4; nt++) {
            int gm = m0 + wm + mt*16 + erow;
            int gc = n0 + wn + nt*8 + ecol;
            float2 v0 = make_float2(acc[mt][nt][0], acc[mt][nt][1]);
            float2 v1 = make_float2(acc[mt][nt][2], acc[mt][nt][3]);
            *(float2*)&C[(size_t)gm*NCOLS + gc]       = v0;
            *(float2*)&C[(size_t)(gm+8)*NCOLS + gc]   = v1;
        }
    }
}

// ---------------------------------------------------------------
// K5: gate per-node GEMM + sigmoid + candidate build
// ---------------------------------------------------------------
__global__ __launch_bounds__(256) void gate_kernel(const float* __restrict__ x,
                                                   const float* __restrict__ state) {
    extern __shared__ float sm[];
    float* sW = sm;              // [KJ][GOUT]
    float* sA = sm + KJ*GOUT;    // [BB][KJ]

    const int n   = blockIdx.x;
    const int tid = threadIdx.x;

    const float* Wn = g_Wg + (size_t)n*KJ*GOUT;
    for (int i = tid*4; i < KJ*GOUT; i += 1024)
        *(float4*)&sW[i] = *(const float4*)&Wn[i];

    const float* xin_n = g_xin + (size_t)n*BB*CIN;
    const float* xg1_n = g_xg1 + (size_t)n*BB*CIN;
    for (int i = tid; i < BB*KJ; i += 256) {
        int b = i / KJ, j = i % KJ;
        sA[i] = (j < CIN) ? xin_n[b*CIN + j] : xg1_n[b*CIN + (j - CIN)];
    }
    __syncthreads();

    const int ty = tid >> 5, tx = tid & 31;
    const int row0 = ty*8;
    const int col0 = tx*4;

    float acc[8][4];
    #pragma unroll
    for (int i = 0; i < 8; i++)
        #pragma unroll
        for (int j = 0; j < 4; j++) acc[i][j] = 0.f;

    for (int kk = 0; kk < KJ; kk++) {
        float4 wv = *(float4*)&sW[kk*GOUT + col0];
        #pragma unroll
        for (int i = 0; i < 8; i++) {
            float av = sA[(row0 + i)*KJ + kk];
            acc[i][0] += av * wv.x;
            acc[i][1] += av * wv.y;
            acc[i][2] += av * wv.z;
            acc[i][3] += av * wv.w;
        }
    }

    #pragma unroll
    for (int j = 0; j < 4; j++) {
        int o = col0 + j;
        float bias = g_bg[n*GOUT + o];
        #pragma unroll
        for (int i = 0; i < 8; i++) {
            int b = row0 + i;
            float v = 1.f / (1.f + expf(-(acc[i][j] + bias)));
            if (o < DOUT) {
                float st = state[((size_t)b*NN + n)*DOUT + o];
                g_cand[((size_t)n*BB + b)*CIN + DIN + o] = v * st;
            } else {
                g_r[((size_t)n*BB + b)*DOUT + (o - DOUT)] = v;
            }
        }
    }
    if (tx == 0) {
        #pragma unroll
        for (int i = 0; i < 8; i++) {
            int b = row0 + i;
            g_cand[((size_t)n*BB + b)*CIN + 0] = x[((size_t)b*NN + n)*DIN + 0];
            g_cand[((size_t)n*BB + b)*CIN + 1] = x[((size_t)b*NN + n)*DIN + 1];
        }
    }
}

// ---------------------------------------------------------------
// K6: update per-node GEMM + tanh + GRU combine
// ---------------------------------------------------------------
__global__ __launch_bounds__(256) void update_kernel(const float* __restrict__ state,
                                                     float* __restrict__ out) {
    extern __shared__ float sm[];
    float* sW = sm;              // [KJ][UOUT]
    float* sA = sm + KJ*UOUT;    // [BB][KJ]

    const int n   = blockIdx.x;
    const int tid = threadIdx.x;

    const float* Wn = g_Wu + (size_t)n*KJ*UOUT;
    for (int i = tid*4; i < KJ*UOUT; i += 1024)
        *(float4*)&sW[i] = *(const float4*)&Wn[i];

    const float* ca_n = g_cand + (size_t)n*BB*CIN;
    const float* cg_n = g_cg1  + (size_t)n*BB*CIN;
    for (int i = tid; i < BB*KJ; i += 256) {
        int b = i / KJ, j = i % KJ;
        sA[i] = (j < CIN) ? ca_n[b*CIN + j] : cg_n[b*CIN + (j - CIN)];
    }
    __syncthreads();

    const int ty = tid >> 5, tx = tid & 31;
    const int row0 = ty*8;
    const int col0 = tx*2;

    float acc[8][2];
    #pragma unroll
    for (int i = 0; i < 8; i++) { acc[i][0] = 0.f; acc[i][1] = 0.f; }

    for (int kk = 0; kk < KJ; kk++) {
        float2 wv = *(float2*)&sW[kk*UOUT + col0];
        #pragma unroll
        for (int i = 0; i < 8; i++) {
            float av = sA[(row0 + i)*KJ + kk];
            acc[i][0] += av * wv.x;
            acc[i][1] += av * wv.y;
        }
    }

    #pragma unroll
    for (int j = 0; j < 2; j++) {
        int o = col0 + j;
        float bias = g_bu[n*UOUT + o];
        #pragma unroll
        for (int i = 0; i < 8; i++) {
            int b = row0 + i;
            float hc = tanhf(acc[i][j] + bias);
            float r  = g_r[((size_t)n*BB + b)*DOUT + o];
            float st = state[((size_t)b*NN + n)*DOUT + o];
            out[((size_t)b*NN + n)*DOUT + o] = r*st + (1.f - r)*hc;
        }
    }
}

// ---------------------------------------------------------------
extern "C" void kernel_launch(void* const* d_in, const int* in_sizes, int n_in,
                              void* d_out, int out_size) {
    const float* x     = (const float*)d_in[0];  // [B,N,2]
    const float* state = (const float*)d_in[1];  // [B,N,64]
    const float* E     = (const float*)d_in[2];  // [N,10]
    const float* gw    = (const float*)d_in[3];  // [10,2,66,128]
    const float* gb    = (const float*)d_in[4];  // [10,128]
    const float* uw    = (const float*)d_in[5];  // [10,2,66,64]
    const float* ub    = (const float*)d_in[6];  // [10,64]
    float* out = (float*)d_out;

    cudaFuncSetAttribute(gate_kernel,   cudaFuncAttributeMaxDynamicSharedMemorySize, (KJ*GOUT + BB*KJ)*4);
    cudaFuncSetAttribute(update_kernel, cudaFuncAttributeMaxDynamicSharedMemorySize, (KJ*UOUT + BB*KJ)*4);
    cudaFuncSetAttribute(hmma_gemm_kernel, cudaFuncAttributeMaxDynamicSharedMemorySize, GEMM_SMEM);

    // 1. adjacency supports -> bf16 hi/lo
    supports_kernel<<<NN, 256>>>(E);
    // 2. concat(x, state) fp32 node-major
    concat_kernel<<<(NN*BB*CIN + 255)/256, 256>>>(x, state);
    // 2b. transpose + bf16 split of xin
    transconv_kernel<<<dim3(NCOLS/64, NN/128), 256>>>(0);
    // 3. pooled weights / biases
    wgen_kernel<<<dim3((KJ*GOUT + 255)/256, NN/16), 256>>>(E, gw, KJ*GOUT, 0);
    wgen_kernel<<<dim3((KJ*UOUT + 255)/256, NN/16), 256>>>(E, uw, KJ*UOUT, 1);
    bgen_kernel<<<(NN*GOUT + 255)/256, 256>>>(E, gb, GOUT, 0);
    bgen_kernel<<<(NN*UOUT + 255)/256, 256>>>(E, ub, UOUT, 1);
    // 4. xg1 = S @ xin  (HMMA tensor cores)
    hmma_gemm_kernel<<<dim3(NCOLS/128, NN/128), 256, GEMM_SMEM>>>(0);
    // 5. gate: z,r + candidate
    gate_kernel<<<NN, 256, (KJ*GOUT + BB*KJ)*4>>>(x, state);
    // 5b. transpose + bf16 split of cand
    transconv_kernel<<<dim3(NCOLS/64, NN/128), 256>>>(1);
    // 6. cg1 = S @ cand (HMMA tensor cores)
    hmma_gemm_kernel<<<dim3(NCOLS/128, NN/128), 256, GEMM_SMEM>>>(1);
    // 7. update: hc + GRU combine -> out
    update_kernel<<<NN, 256, (KJ*UOUT + BB*KJ)*4>>>(state, out);
}